// round 15
// baseline (speedup 1.0000x reference)
#include <cuda_runtime.h>
#include <cstdint>

// Problem constants (fixed by the dataset: V=8192 vertices, E=40000 tets)
#define V 8192
#define E 40000
#define ROWS_PER_TILE 4
#define COL_SPLIT 2
#define SEG_F4 (V / 4 / COL_SPLIT)            // 1024 float4 per column segment
#define MV_BLOCKS ((V / ROWS_PER_TILE) * COL_SPLIT)  // 4096 matvec blocks
#define EL_BLOCKS ((E + 255) / 256)           // 157 elastic blocks
#define TOTAL_BLOCKS (MV_BLOCKS + EL_BLOCKS)  // 4253
#define MV_ITERS (SEG_F4 / 256)               // 4 iterations

// Scratch (device globals — no allocations allowed). 16B-aligned for float4 LDG.
__device__ __align__(16) float g_dx[V];
__device__ __align__(16) float g_dy[V];
__device__ __align__(16) float g_dz[V];
__device__ double g_kin_accum;    // sum_i delta_i . (M delta)_i   (atomic)
__device__ double g_el_accum;     // sum_e psi_e * measure_e       (atomic)
__device__ unsigned int g_done;   // completion counter (all TOTAL_BLOCKS)

// ---------------------------------------------------------------------------
// Kernel 1: delta = next_position - (position + velocity*dt + ext_acc*dt^2)
// (SoA for float4 loads). Thread 0 resets accumulators (stream-ordered
// before kernel 2). Tiny: 32 blocks.
// ---------------------------------------------------------------------------
__global__ void delta_kernel(const float* __restrict__ next_pos,
                             const float* __restrict__ pos,
                             const float* __restrict__ vel,
                             const float* __restrict__ ext,
                             const float* __restrict__ ts_ptr)
{
    int v = blockIdx.x * blockDim.x + threadIdx.x;
    if (v == 0) {
        g_kin_accum = 0.0;
        g_el_accum  = 0.0;
        g_done      = 0u;
    }
    if (v >= V) return;
    float dt  = ts_ptr[0];
    float dt2 = dt * dt;
    int b = v * 3;
    g_dx[v] = next_pos[b + 0] - (pos[b + 0] + vel[b + 0] * dt + ext[b + 0] * dt2);
    g_dy[v] = next_pos[b + 1] - (pos[b + 1] + vel[b + 1] * dt + ext[b + 1] * dt2);
    g_dz[v] = next_pos[b + 2] - (pos[b + 2] + vel[b + 2] * dt + ext[b + 2] * dt2);
}

// ---------------------------------------------------------------------------
// Kernel 2 (mega): blocks [0, 4096) = matvec tiles of 4 rows x 4096 cols
// (bid pair (2k, 2k+1) covers one contiguous 128 KB region of M); blocks
// [4096, 4253) = elastic element blocks packed into the final wave.
// Register diet for 6 blocks/SM: ONE base pointer + constant row offsets,
// FMA blocks grouped per delta-component so only one of x/y/z is live at a
// time (live set ~38 regs). __ldcs streams M past L1 so delta stays
// L1-resident. Last of all 4253 blocks (ticket) writes the 3 outputs.
// elements is int32 on device (JAX x64 disabled); clamped defensively.
// ---------------------------------------------------------------------------
__global__ __launch_bounds__(256, 6) void mega_kernel(
    const float* __restrict__ M,
    const float* __restrict__ next_pos,
    const int* __restrict__ elems,
    const float* __restrict__ poly,
    const float* __restrict__ measure,
    const float* __restrict__ lam,
    const float* __restrict__ mu,
    const float* __restrict__ ts_ptr,
    float* __restrict__ out)
{
    const int bid = blockIdx.x;

    if (bid < MV_BLOCKS) {
        // ------------------------- matvec tile path -------------------------
        const int row0  = (bid >> 1) * ROWS_PER_TILE;
        const int cbase = (bid & 1) * SEG_F4;            // float4 units
        // single base pointer; row offsets are compile-time constants (V/4
        // float4 per row) -> minimal addressing registers
        const float4* __restrict__ Mb =
            reinterpret_cast<const float4*>(M + (size_t)row0 * V) + cbase;
        const float4* __restrict__ DX = reinterpret_cast<const float4*>(g_dx) + cbase;
        const float4* __restrict__ DY = reinterpret_cast<const float4*>(g_dy) + cbase;
        const float4* __restrict__ DZ = reinterpret_cast<const float4*>(g_dz) + cbase;

        float a00=0.f,a01=0.f,a02=0.f, a10=0.f,a11=0.f,a12=0.f;
        float a20=0.f,a21=0.f,a22=0.f, a30=0.f,a31=0.f,a32=0.f;

#pragma unroll
        for (int it = 0; it < MV_ITERS; ++it) {
            int idx = threadIdx.x + it * 256;
            float4 m0 = __ldcs(&Mb[idx + 0 * (V / 4)]);
            float4 m1 = __ldcs(&Mb[idx + 1 * (V / 4)]);
            float4 m2 = __ldcs(&Mb[idx + 2 * (V / 4)]);
            float4 m3 = __ldcs(&Mb[idx + 3 * (V / 4)]);

            // x block
            float4 v = DX[idx];
            a00 += m0.x*v.x + m0.y*v.y + m0.z*v.z + m0.w*v.w;
            a10 += m1.x*v.x + m1.y*v.y + m1.z*v.z + m1.w*v.w;
            a20 += m2.x*v.x + m2.y*v.y + m2.z*v.z + m2.w*v.w;
            a30 += m3.x*v.x + m3.y*v.y + m3.z*v.z + m3.w*v.w;
            // y block
            v = DY[idx];
            a01 += m0.x*v.x + m0.y*v.y + m0.z*v.z + m0.w*v.w;
            a11 += m1.x*v.x + m1.y*v.y + m1.z*v.z + m1.w*v.w;
            a21 += m2.x*v.x + m2.y*v.y + m2.z*v.z + m2.w*v.w;
            a31 += m3.x*v.x + m3.y*v.y + m3.z*v.z + m3.w*v.w;
            // z block
            v = DZ[idx];
            a02 += m0.x*v.x + m0.y*v.y + m0.z*v.z + m0.w*v.w;
            a12 += m1.x*v.x + m1.y*v.y + m1.z*v.z + m1.w*v.w;
            a22 += m2.x*v.x + m2.y*v.y + m2.z*v.z + m2.w*v.w;
            a32 += m3.x*v.x + m3.y*v.y + m3.z*v.z + m3.w*v.w;
        }

        // reduce 12 partials: warp shuffles then smem
#pragma unroll
        for (int off = 16; off > 0; off >>= 1) {
            a00 += __shfl_down_sync(0xFFFFFFFFu, a00, off);
            a01 += __shfl_down_sync(0xFFFFFFFFu, a01, off);
            a02 += __shfl_down_sync(0xFFFFFFFFu, a02, off);
            a10 += __shfl_down_sync(0xFFFFFFFFu, a10, off);
            a11 += __shfl_down_sync(0xFFFFFFFFu, a11, off);
            a12 += __shfl_down_sync(0xFFFFFFFFu, a12, off);
            a20 += __shfl_down_sync(0xFFFFFFFFu, a20, off);
            a21 += __shfl_down_sync(0xFFFFFFFFu, a21, off);
            a22 += __shfl_down_sync(0xFFFFFFFFu, a22, off);
            a30 += __shfl_down_sync(0xFFFFFFFFu, a30, off);
            a31 += __shfl_down_sync(0xFFFFFFFFu, a31, off);
            a32 += __shfl_down_sync(0xFFFFFFFFu, a32, off);
        }
        __shared__ float sh[12][8];
        int lane = threadIdx.x & 31;
        int warp = threadIdx.x >> 5;
        if (lane == 0) {
            sh[0][warp]=a00; sh[1][warp]=a01; sh[2][warp]=a02;
            sh[3][warp]=a10; sh[4][warp]=a11; sh[5][warp]=a12;
            sh[6][warp]=a20; sh[7][warp]=a21; sh[8][warp]=a22;
            sh[9][warp]=a30; sh[10][warp]=a31; sh[11][warp]=a32;
        }
        __syncthreads();

        if (threadIdx.x < 12) {
            float s = 0.f;
#pragma unroll
            for (int w = 0; w < 8; ++w) s += sh[threadIdx.x][w];
            sh[threadIdx.x][0] = s;
        }
        __syncthreads();

        if (threadIdx.x == 0) {
            double contrib = 0.0;
#pragma unroll
            for (int r = 0; r < ROWS_PER_TILE; ++r) {
                int row = row0 + r;
                contrib += (double)g_dx[row] * sh[r*3+0][0]
                         + (double)g_dy[row] * sh[r*3+1][0]
                         + (double)g_dz[row] * sh[r*3+2][0];
            }
            atomicAdd(&g_kin_accum, contrib);
        }
    } else {
        // -------------------------- elastic path ---------------------------
        int e = (bid - MV_BLOCKS) * 256 + threadIdx.x;
        float val = 0.f;
        if (e < E) {
            float F00 = 0.f, F01 = 0.f, F02 = 0.f;
            float F10 = 0.f, F11 = 0.f, F12 = 0.f;
            float F20 = 0.f, F21 = 0.f, F22 = 0.f;
            const int4 ev = reinterpret_cast<const int4*>(elems)[e];
            int vidx[4] = { ev.x, ev.y, ev.z, ev.w };
            const float4* __restrict__ pl4 = reinterpret_cast<const float4*>(poly) + (size_t)e * 4;
#pragma unroll
            for (int f = 0; f < 4; ++f) {
                int vi = vidx[f];
                vi = vi < 0 ? 0 : (vi >= V ? V - 1 : vi);   // defensive clamp
                const float* p = next_pos + (size_t)vi * 3;
                float px = p[0], py = p[1], pz = p[2];
                float4 pl = pl4[f];
                float p0 = pl.x, p1 = pl.y, p2 = pl.z;
                F00 += px * p0; F01 += px * p1; F02 += px * p2;
                F10 += py * p0; F11 += py * p1; F12 += py * p2;
                F20 += pz * p0; F21 += pz * p1; F22 += pz * p2;
            }
            float Ic = F00*F00 + F01*F01 + F02*F02
                     + F10*F10 + F11*F11 + F12*F12
                     + F20*F20 + F21*F21 + F22*F22;
            float J = F00 * (F11 * F22 - F12 * F21)
                    - F01 * (F10 * F22 - F12 * F20)
                    + F02 * (F10 * F21 - F11 * F20);
            float l = lam[e], m = mu[e];
            float alpha = 0.75f * m / l + 1.0f;
            float Icv = fmaxf(Ic + 1.0f, 0.0f);
            float d = J - alpha;
            float psi = 0.5f * m * (Ic - 3.0f)
                      + 0.5f * l * d * d
                      - 0.5f * m * logf(Icv + 1e-30f);
            val = psi * measure[(size_t)e * 4 + 3];
        }

#pragma unroll
        for (int off = 16; off > 0; off >>= 1)
            val += __shfl_down_sync(0xFFFFFFFFu, val, off);
        __shared__ float she[8];
        int lane = threadIdx.x & 31;
        int warp = threadIdx.x >> 5;
        if (lane == 0) she[warp] = val;
        __syncthreads();
        if (threadIdx.x == 0) {
            float s = 0.f;
#pragma unroll
            for (int w = 0; w < 8; ++w) s += she[w];
            atomicAdd(&g_el_accum, (double)s);
        }
    }

    // ---------------- completion ticket + final output write ----------------
    if (threadIdx.x == 0) {
        __threadfence();
        unsigned int t = atomicAdd(&g_done, 1u);
        if (t == (unsigned int)(TOTAL_BLOCKS - 1)) {
            __threadfence();
            double dt = (double)ts_ptr[0];
            double inv_h = 1.0 / dt;
            double coeff = inv_h * inv_h * 0.5;
            double kin = coeff * g_kin_accum;
            double el  = g_el_accum;
            out[0] = (float)(kin + el);
            out[1] = (float)kin;
            out[2] = (float)el;
        }
    }
}

// ---------------------------------------------------------------------------
// Launch
// ---------------------------------------------------------------------------
extern "C" void kernel_launch(void* const* d_in, const int* in_sizes, int n_in,
                              void* d_out, int out_size)
{
    const float* next_pos = (const float*)d_in[0];
    const float* pos      = (const float*)d_in[1];
    const float* vel      = (const float*)d_in[2];
    const float* ext      = (const float*)d_in[3];
    const float* M        = (const float*)d_in[4];
    const int*   elems    = (const int*)d_in[5];
    const float* poly     = (const float*)d_in[6];
    const float* measure  = (const float*)d_in[7];
    const float* lam      = (const float*)d_in[8];
    const float* mu       = (const float*)d_in[9];
    const float* ts       = (const float*)d_in[10];
    float* out = (float*)d_out;

    delta_kernel<<<(V + 255) / 256, 256>>>(next_pos, pos, vel, ext, ts);
    mega_kernel<<<TOTAL_BLOCKS, 256>>>(M, next_pos, elems, poly, measure,
                                       lam, mu, ts, out);
}

// round 16
// speedup vs baseline: 1.1103x; 1.1103x over previous
#include <cuda_runtime.h>
#include <cstdint>

// Problem constants (fixed by the dataset: V=8192 vertices, E=40000 tets)
#define V 8192
#define E 40000
#define ROWS_PER_TILE 4
#define MV_TILES (V / ROWS_PER_TILE)          // 2048 matvec tiles
#define EL_BLOCKS ((E + 255) / 256)           // 157 elastic blocks
#define TOTAL_BLOCKS (MV_TILES + EL_BLOCKS)   // 2205
#define DELTA_BLOCKS (V / 256)                // 32 blocks compute delta first

// Scratch (device globals — no allocations allowed). 16B-aligned for float4 LDG.
// All counters/accums are reset by the ticket-winning block at the END of each
// launch, so every graph replay starts clean (first launch: zero-init).
__device__ __align__(16) float g_dx[V];
__device__ __align__(16) float g_dy[V];
__device__ __align__(16) float g_dz[V];
__device__ double g_kin_accum;               // sum_i delta_i . (M delta)_i
__device__ double g_el_accum;                // sum_e psi_e * measure_e
__device__ unsigned int g_done;              // completion ticket
__device__ volatile unsigned int g_delta_ready;  // delta-phase counter (0..32)

// ---------------------------------------------------------------------------
// Single mega kernel.
//   bids [0, 32):    ALSO compute delta chunk first (release-fenced counter)
//   all blocks:      spin (thread 0 + backoff) until all 32 delta chunks done
//   bids [0, 2048):  matvec tile, 4 rows x 8192 cols — the measured-optimal
//                    plain 7-LDG/48-FFMA loop, __ldcs on M, 5 blocks/SM
//   bids [2048, 2205): elastic element blocks (packed into the final wave)
//   last block (ticket): writes the 3 outputs, then resets all state.
// Deadlock-safe: delta bids 0-31 are in wave 1 (740 resident blocks).
// Coherence-safe: L1 is flushed at launch, delta producers fence before the
// counter bump, so post-flag delta reads hit valid L2 data.
// elements is int32 on device (JAX x64 disabled); clamped defensively.
// ---------------------------------------------------------------------------
__global__ __launch_bounds__(256, 5) void mega_kernel(
    const float* __restrict__ M,
    const float* __restrict__ next_pos,
    const float* __restrict__ pos,
    const float* __restrict__ vel,
    const float* __restrict__ ext,
    const int* __restrict__ elems,
    const float* __restrict__ poly,
    const float* __restrict__ measure,
    const float* __restrict__ lam,
    const float* __restrict__ mu,
    const float* __restrict__ ts_ptr,
    float* __restrict__ out)
{
    const int bid = blockIdx.x;

    // ---------------------- phase 0: delta (bids 0-31) ----------------------
    if (bid < DELTA_BLOCKS) {
        int v = bid * 256 + threadIdx.x;   // covers [0, 8192) exactly
        float dt  = ts_ptr[0];
        float dt2 = dt * dt;
        int b = v * 3;
        g_dx[v] = next_pos[b + 0] - (pos[b + 0] + vel[b + 0] * dt + ext[b + 0] * dt2);
        g_dy[v] = next_pos[b + 1] - (pos[b + 1] + vel[b + 1] * dt + ext[b + 1] * dt2);
        g_dz[v] = next_pos[b + 2] - (pos[b + 2] + vel[b + 2] * dt + ext[b + 2] * dt2);
        __syncthreads();
        if (threadIdx.x == 0) {
            __threadfence();   // release: delta visible before counter bump
            atomicAdd((unsigned int*)&g_delta_ready, 1u);
        }
    }

    // ------------------- phase 0.5: wait for all deltas ---------------------
    if (threadIdx.x == 0) {
        while (g_delta_ready < (unsigned int)DELTA_BLOCKS)
            __nanosleep(100);
    }
    __syncthreads();

    if (bid < MV_TILES) {
        // ------------------------- matvec tile path -------------------------
        const int row0 = bid * ROWS_PER_TILE;
        const float4* __restrict__ M0 = reinterpret_cast<const float4*>(M + (size_t)(row0 + 0) * V);
        const float4* __restrict__ M1 = reinterpret_cast<const float4*>(M + (size_t)(row0 + 1) * V);
        const float4* __restrict__ M2 = reinterpret_cast<const float4*>(M + (size_t)(row0 + 2) * V);
        const float4* __restrict__ M3 = reinterpret_cast<const float4*>(M + (size_t)(row0 + 3) * V);
        const float4* __restrict__ DX = reinterpret_cast<const float4*>(g_dx);
        const float4* __restrict__ DY = reinterpret_cast<const float4*>(g_dy);
        const float4* __restrict__ DZ = reinterpret_cast<const float4*>(g_dz);

        float a00=0.f,a01=0.f,a02=0.f, a10=0.f,a11=0.f,a12=0.f;
        float a20=0.f,a21=0.f,a22=0.f, a30=0.f,a31=0.f,a32=0.f;

#pragma unroll
        for (int it = 0; it < (V / 4) / 256; ++it) {
            int idx = threadIdx.x + it * 256;
            float4 m0 = __ldcs(&M0[idx]);
            float4 m1 = __ldcs(&M1[idx]);
            float4 m2 = __ldcs(&M2[idx]);
            float4 m3 = __ldcs(&M3[idx]);
            float4 x  = DX[idx];
            float4 y  = DY[idx];
            float4 z  = DZ[idx];

            a00 += m0.x*x.x + m0.y*x.y + m0.z*x.z + m0.w*x.w;
            a01 += m0.x*y.x + m0.y*y.y + m0.z*y.z + m0.w*y.w;
            a02 += m0.x*z.x + m0.y*z.y + m0.z*z.z + m0.w*z.w;

            a10 += m1.x*x.x + m1.y*x.y + m1.z*x.z + m1.w*x.w;
            a11 += m1.x*y.x + m1.y*y.y + m1.z*y.z + m1.w*y.w;
            a12 += m1.x*z.x + m1.y*z.y + m1.z*z.z + m1.w*z.w;

            a20 += m2.x*x.x + m2.y*x.y + m2.z*x.z + m2.w*x.w;
            a21 += m2.x*y.x + m2.y*y.y + m2.z*y.z + m2.w*y.w;
            a22 += m2.x*z.x + m2.y*z.y + m2.z*z.z + m2.w*z.w;

            a30 += m3.x*x.x + m3.y*x.y + m3.z*x.z + m3.w*x.w;
            a31 += m3.x*y.x + m3.y*y.y + m3.z*y.z + m3.w*y.w;
            a32 += m3.x*z.x + m3.y*z.y + m3.z*z.z + m3.w*z.w;
        }

        // reduce 12 partials: warp shuffles then smem
#pragma unroll
        for (int off = 16; off > 0; off >>= 1) {
            a00 += __shfl_down_sync(0xFFFFFFFFu, a00, off);
            a01 += __shfl_down_sync(0xFFFFFFFFu, a01, off);
            a02 += __shfl_down_sync(0xFFFFFFFFu, a02, off);
            a10 += __shfl_down_sync(0xFFFFFFFFu, a10, off);
            a11 += __shfl_down_sync(0xFFFFFFFFu, a11, off);
            a12 += __shfl_down_sync(0xFFFFFFFFu, a12, off);
            a20 += __shfl_down_sync(0xFFFFFFFFu, a20, off);
            a21 += __shfl_down_sync(0xFFFFFFFFu, a21, off);
            a22 += __shfl_down_sync(0xFFFFFFFFu, a22, off);
            a30 += __shfl_down_sync(0xFFFFFFFFu, a30, off);
            a31 += __shfl_down_sync(0xFFFFFFFFu, a31, off);
            a32 += __shfl_down_sync(0xFFFFFFFFu, a32, off);
        }
        __shared__ float sh[12][8];
        int lane = threadIdx.x & 31;
        int warp = threadIdx.x >> 5;
        if (lane == 0) {
            sh[0][warp]=a00; sh[1][warp]=a01; sh[2][warp]=a02;
            sh[3][warp]=a10; sh[4][warp]=a11; sh[5][warp]=a12;
            sh[6][warp]=a20; sh[7][warp]=a21; sh[8][warp]=a22;
            sh[9][warp]=a30; sh[10][warp]=a31; sh[11][warp]=a32;
        }
        __syncthreads();

        if (threadIdx.x < 12) {
            float s = 0.f;
#pragma unroll
            for (int w = 0; w < 8; ++w) s += sh[threadIdx.x][w];
            sh[threadIdx.x][0] = s;
        }
        __syncthreads();

        if (threadIdx.x == 0) {
            double contrib = 0.0;
#pragma unroll
            for (int r = 0; r < ROWS_PER_TILE; ++r) {
                int row = row0 + r;
                contrib += (double)g_dx[row] * sh[r*3+0][0]
                         + (double)g_dy[row] * sh[r*3+1][0]
                         + (double)g_dz[row] * sh[r*3+2][0];
            }
            atomicAdd(&g_kin_accum, contrib);
        }
    } else {
        // -------------------------- elastic path ---------------------------
        int e = (bid - MV_TILES) * 256 + threadIdx.x;
        float val = 0.f;
        if (e < E) {
            float F00 = 0.f, F01 = 0.f, F02 = 0.f;
            float F10 = 0.f, F11 = 0.f, F12 = 0.f;
            float F20 = 0.f, F21 = 0.f, F22 = 0.f;
            const int4 ev = reinterpret_cast<const int4*>(elems)[e];
            int vidx[4] = { ev.x, ev.y, ev.z, ev.w };
            const float4* __restrict__ pl4 = reinterpret_cast<const float4*>(poly) + (size_t)e * 4;
#pragma unroll
            for (int f = 0; f < 4; ++f) {
                int vi = vidx[f];
                vi = vi < 0 ? 0 : (vi >= V ? V - 1 : vi);   // defensive clamp
                const float* p = next_pos + (size_t)vi * 3;
                float px = p[0], py = p[1], pz = p[2];
                float4 pl = pl4[f];
                float p0 = pl.x, p1 = pl.y, p2 = pl.z;
                F00 += px * p0; F01 += px * p1; F02 += px * p2;
                F10 += py * p0; F11 += py * p1; F12 += py * p2;
                F20 += pz * p0; F21 += pz * p1; F22 += pz * p2;
            }
            float Ic = F00*F00 + F01*F01 + F02*F02
                     + F10*F10 + F11*F11 + F12*F12
                     + F20*F20 + F21*F21 + F22*F22;
            float J = F00 * (F11 * F22 - F12 * F21)
                    - F01 * (F10 * F22 - F12 * F20)
                    + F02 * (F10 * F21 - F11 * F20);
            float l = lam[e], m = mu[e];
            float alpha = 0.75f * m / l + 1.0f;
            float Icv = fmaxf(Ic + 1.0f, 0.0f);
            float d = J - alpha;
            float psi = 0.5f * m * (Ic - 3.0f)
                      + 0.5f * l * d * d
                      - 0.5f * m * logf(Icv + 1e-30f);
            val = psi * measure[(size_t)e * 4 + 3];
        }

#pragma unroll
        for (int off = 16; off > 0; off >>= 1)
            val += __shfl_down_sync(0xFFFFFFFFu, val, off);
        __shared__ float she[8];
        int lane = threadIdx.x & 31;
        int warp = threadIdx.x >> 5;
        if (lane == 0) she[warp] = val;
        __syncthreads();
        if (threadIdx.x == 0) {
            float s = 0.f;
#pragma unroll
            for (int w = 0; w < 8; ++w) s += she[w];
            atomicAdd(&g_el_accum, (double)s);
        }
    }

    // -------- completion ticket: last block writes outputs + resets --------
    if (threadIdx.x == 0) {
        __threadfence();
        unsigned int t = atomicAdd(&g_done, 1u);
        if (t == (unsigned int)(TOTAL_BLOCKS - 1)) {
            __threadfence();
            double dt = (double)ts_ptr[0];
            double inv_h = 1.0 / dt;
            double coeff = inv_h * inv_h * 0.5;
            double kin = coeff * g_kin_accum;
            double el  = g_el_accum;
            out[0] = (float)(kin + el);
            out[1] = (float)kin;
            out[2] = (float)el;
            // reset state for the next graph replay (stream-ordered)
            g_kin_accum = 0.0;
            g_el_accum  = 0.0;
            *(unsigned int*)&g_delta_ready = 0u;
            __threadfence();
            g_done = 0u;
        }
    }
}

// ---------------------------------------------------------------------------
// Launch — a single kernel; the delta dependency is resolved in-kernel.
// ---------------------------------------------------------------------------
extern "C" void kernel_launch(void* const* d_in, const int* in_sizes, int n_in,
                              void* d_out, int out_size)
{
    const float* next_pos = (const float*)d_in[0];
    const float* pos      = (const float*)d_in[1];
    const float* vel      = (const float*)d_in[2];
    const float* ext      = (const float*)d_in[3];
    const float* M        = (const float*)d_in[4];
    const int*   elems    = (const int*)d_in[5];
    const float* poly     = (const float*)d_in[6];
    const float* measure  = (const float*)d_in[7];
    const float* lam      = (const float*)d_in[8];
    const float* mu       = (const float*)d_in[9];
    const float* ts       = (const float*)d_in[10];
    float* out = (float*)d_out;

    mega_kernel<<<TOTAL_BLOCKS, 256>>>(M, next_pos, pos, vel, ext,
                                       elems, poly, measure, lam, mu, ts, out);
}

// round 17
// speedup vs baseline: 1.1925x; 1.0740x over previous
#include <cuda_runtime.h>
#include <cstdint>

// Problem constants (fixed by the dataset: V=8192 vertices, E=40000 tets)
#define V 8192
#define E 40000
#define ROWS_PER_TILE 4
#define MV_TILES (V / ROWS_PER_TILE)          // 2048 matvec tiles
#define EL_BLOCKS ((E + 255) / 256)           // 157 elastic blocks
#define TOTAL_BLOCKS (MV_TILES + EL_BLOCKS)   // 2205

// Scratch (device globals — no allocations allowed). 16B-aligned for float4 LDG.
__device__ __align__(16) float g_dx[V];
__device__ __align__(16) float g_dy[V];
__device__ __align__(16) float g_dz[V];
__device__ double g_kin_accum;    // sum_i delta_i . (M delta)_i   (atomic)
__device__ double g_el_accum;     // sum_e psi_e * measure_e       (atomic)
__device__ unsigned int g_done;   // completion counter (all TOTAL_BLOCKS)

// ---------------------------------------------------------------------------
// Kernel 1: delta = next_position - (position + velocity*dt + ext_acc*dt^2)
// (SoA for float4 loads). Thread 0 resets accumulators. Signals dependent
// launch (PDL) after its stores so the mega kernel's blocks can begin
// prefetching M while delta finishes draining.
// ---------------------------------------------------------------------------
__global__ void delta_kernel(const float* __restrict__ next_pos,
                             const float* __restrict__ pos,
                             const float* __restrict__ vel,
                             const float* __restrict__ ext,
                             const float* __restrict__ ts_ptr)
{
    int v = blockIdx.x * blockDim.x + threadIdx.x;
    if (v == 0) {
        g_kin_accum = 0.0;
        g_el_accum  = 0.0;
        g_done      = 0u;
    }
    if (v < V) {
        float dt  = ts_ptr[0];
        float dt2 = dt * dt;
        int b = v * 3;
        g_dx[v] = next_pos[b + 0] - (pos[b + 0] + vel[b + 0] * dt + ext[b + 0] * dt2);
        g_dy[v] = next_pos[b + 1] - (pos[b + 1] + vel[b + 1] * dt + ext[b + 1] * dt2);
        g_dz[v] = next_pos[b + 2] - (pos[b + 2] + vel[b + 2] * dt + ext[b + 2] * dt2);
    }
    // allow the dependent (mega) grid to launch now; its griddepcontrol.wait
    // still guarantees full visibility of this kernel's writes.
    asm volatile("griddepcontrol.launch_dependents;");
}

// ---------------------------------------------------------------------------
// Kernel 2 (mega, PDL secondary): identical compute to the 57.86us best.
//   bids [0, 2048):   matvec tiles (4 rows x 8192 cols, plain 7-LDG/48-FFMA
//                     loop, __ldcs on M, 5 blocks/SM)
//   bids [2048, 2205): elastic element blocks (packed into the final wave)
// New: before griddepcontrol.wait, matvec blocks prefetch their first two
// iterations of M into L2 — the HBM pipes are idle during the delta window,
// so wave-1's first loads become L2 hits (~free ~25MB warmup).
// elements is int32 on device (JAX x64 disabled); clamped defensively.
// ---------------------------------------------------------------------------
__global__ __launch_bounds__(256, 5) void mega_kernel(
    const float* __restrict__ M,
    const float* __restrict__ next_pos,
    const int* __restrict__ elems,
    const float* __restrict__ poly,
    const float* __restrict__ measure,
    const float* __restrict__ lam,
    const float* __restrict__ mu,
    const float* __restrict__ ts_ptr,
    float* __restrict__ out)
{
    const int bid = blockIdx.x;

    if (bid < MV_TILES) {
        // ------------------------- matvec tile path -------------------------
        const int row0 = bid * ROWS_PER_TILE;
        const float4* __restrict__ M0 = reinterpret_cast<const float4*>(M + (size_t)(row0 + 0) * V);
        const float4* __restrict__ M1 = reinterpret_cast<const float4*>(M + (size_t)(row0 + 1) * V);
        const float4* __restrict__ M2 = reinterpret_cast<const float4*>(M + (size_t)(row0 + 2) * V);
        const float4* __restrict__ M3 = reinterpret_cast<const float4*>(M + (size_t)(row0 + 3) * V);
        const float4* __restrict__ DX = reinterpret_cast<const float4*>(g_dx);
        const float4* __restrict__ DY = reinterpret_cast<const float4*>(g_dy);
        const float4* __restrict__ DZ = reinterpret_cast<const float4*>(g_dz);

        // L2 prefetch of iterations 0 and 1 of M (input-only: safe pre-wait)
        {
            int i0 = threadIdx.x;
            int i1 = threadIdx.x + 256;
            asm volatile("prefetch.global.L2 [%0];" :: "l"(&M0[i0]));
            asm volatile("prefetch.global.L2 [%0];" :: "l"(&M1[i0]));
            asm volatile("prefetch.global.L2 [%0];" :: "l"(&M2[i0]));
            asm volatile("prefetch.global.L2 [%0];" :: "l"(&M3[i0]));
            asm volatile("prefetch.global.L2 [%0];" :: "l"(&M0[i1]));
            asm volatile("prefetch.global.L2 [%0];" :: "l"(&M1[i1]));
            asm volatile("prefetch.global.L2 [%0];" :: "l"(&M2[i1]));
            asm volatile("prefetch.global.L2 [%0];" :: "l"(&M3[i1]));
        }
        // wait for delta_kernel's writes (delta arrays + counter resets)
        asm volatile("griddepcontrol.wait;" ::: "memory");

        float a00=0.f,a01=0.f,a02=0.f, a10=0.f,a11=0.f,a12=0.f;
        float a20=0.f,a21=0.f,a22=0.f, a30=0.f,a31=0.f,a32=0.f;

#pragma unroll
        for (int it = 0; it < (V / 4) / 256; ++it) {
            int idx = threadIdx.x + it * 256;
            float4 m0 = __ldcs(&M0[idx]);
            float4 m1 = __ldcs(&M1[idx]);
            float4 m2 = __ldcs(&M2[idx]);
            float4 m3 = __ldcs(&M3[idx]);
            float4 x  = DX[idx];
            float4 y  = DY[idx];
            float4 z  = DZ[idx];

            a00 += m0.x*x.x + m0.y*x.y + m0.z*x.z + m0.w*x.w;
            a01 += m0.x*y.x + m0.y*y.y + m0.z*y.z + m0.w*y.w;
            a02 += m0.x*z.x + m0.y*z.y + m0.z*z.z + m0.w*z.w;

            a10 += m1.x*x.x + m1.y*x.y + m1.z*x.z + m1.w*x.w;
            a11 += m1.x*y.x + m1.y*y.y + m1.z*y.z + m1.w*y.w;
            a12 += m1.x*z.x + m1.y*z.y + m1.z*z.z + m1.w*z.w;

            a20 += m2.x*x.x + m2.y*x.y + m2.z*x.z + m2.w*x.w;
            a21 += m2.x*y.x + m2.y*y.y + m2.z*y.z + m2.w*y.w;
            a22 += m2.x*z.x + m2.y*z.y + m2.z*z.z + m2.w*z.w;

            a30 += m3.x*x.x + m3.y*x.y + m3.z*x.z + m3.w*x.w;
            a31 += m3.x*y.x + m3.y*y.y + m3.z*y.z + m3.w*y.w;
            a32 += m3.x*z.x + m3.y*z.y + m3.z*z.z + m3.w*z.w;
        }

        // reduce 12 partials: warp shuffles then smem
#pragma unroll
        for (int off = 16; off > 0; off >>= 1) {
            a00 += __shfl_down_sync(0xFFFFFFFFu, a00, off);
            a01 += __shfl_down_sync(0xFFFFFFFFu, a01, off);
            a02 += __shfl_down_sync(0xFFFFFFFFu, a02, off);
            a10 += __shfl_down_sync(0xFFFFFFFFu, a10, off);
            a11 += __shfl_down_sync(0xFFFFFFFFu, a11, off);
            a12 += __shfl_down_sync(0xFFFFFFFFu, a12, off);
            a20 += __shfl_down_sync(0xFFFFFFFFu, a20, off);
            a21 += __shfl_down_sync(0xFFFFFFFFu, a21, off);
            a22 += __shfl_down_sync(0xFFFFFFFFu, a22, off);
            a30 += __shfl_down_sync(0xFFFFFFFFu, a30, off);
            a31 += __shfl_down_sync(0xFFFFFFFFu, a31, off);
            a32 += __shfl_down_sync(0xFFFFFFFFu, a32, off);
        }
        __shared__ float sh[12][8];
        int lane = threadIdx.x & 31;
        int warp = threadIdx.x >> 5;
        if (lane == 0) {
            sh[0][warp]=a00; sh[1][warp]=a01; sh[2][warp]=a02;
            sh[3][warp]=a10; sh[4][warp]=a11; sh[5][warp]=a12;
            sh[6][warp]=a20; sh[7][warp]=a21; sh[8][warp]=a22;
            sh[9][warp]=a30; sh[10][warp]=a31; sh[11][warp]=a32;
        }
        __syncthreads();

        if (threadIdx.x < 12) {
            float s = 0.f;
#pragma unroll
            for (int w = 0; w < 8; ++w) s += sh[threadIdx.x][w];
            sh[threadIdx.x][0] = s;
        }
        __syncthreads();

        if (threadIdx.x == 0) {
            double contrib = 0.0;
#pragma unroll
            for (int r = 0; r < ROWS_PER_TILE; ++r) {
                int row = row0 + r;
                contrib += (double)g_dx[row] * sh[r*3+0][0]
                         + (double)g_dy[row] * sh[r*3+1][0]
                         + (double)g_dz[row] * sh[r*3+2][0];
            }
            atomicAdd(&g_kin_accum, contrib);
        }
    } else {
        // -------------------------- elastic path ---------------------------
        // still must wait: g_el_accum/g_done are reset by delta_kernel
        asm volatile("griddepcontrol.wait;" ::: "memory");

        int e = (bid - MV_TILES) * 256 + threadIdx.x;
        float val = 0.f;
        if (e < E) {
            float F00 = 0.f, F01 = 0.f, F02 = 0.f;
            float F10 = 0.f, F11 = 0.f, F12 = 0.f;
            float F20 = 0.f, F21 = 0.f, F22 = 0.f;
            const int4 ev = reinterpret_cast<const int4*>(elems)[e];
            int vidx[4] = { ev.x, ev.y, ev.z, ev.w };
            const float4* __restrict__ pl4 = reinterpret_cast<const float4*>(poly) + (size_t)e * 4;
#pragma unroll
            for (int f = 0; f < 4; ++f) {
                int vi = vidx[f];
                vi = vi < 0 ? 0 : (vi >= V ? V - 1 : vi);   // defensive clamp
                const float* p = next_pos + (size_t)vi * 3;
                float px = p[0], py = p[1], pz = p[2];
                float4 pl = pl4[f];
                float p0 = pl.x, p1 = pl.y, p2 = pl.z;
                F00 += px * p0; F01 += px * p1; F02 += px * p2;
                F10 += py * p0; F11 += py * p1; F12 += py * p2;
                F20 += pz * p0; F21 += pz * p1; F22 += pz * p2;
            }
            float Ic = F00*F00 + F01*F01 + F02*F02
                     + F10*F10 + F11*F11 + F12*F12
                     + F20*F20 + F21*F21 + F22*F22;
            float J = F00 * (F11 * F22 - F12 * F21)
                    - F01 * (F10 * F22 - F12 * F20)
                    + F02 * (F10 * F21 - F11 * F20);
            float l = lam[e], m = mu[e];
            float alpha = 0.75f * m / l + 1.0f;
            float Icv = fmaxf(Ic + 1.0f, 0.0f);
            float d = J - alpha;
            float psi = 0.5f * m * (Ic - 3.0f)
                      + 0.5f * l * d * d
                      - 0.5f * m * logf(Icv + 1e-30f);
            val = psi * measure[(size_t)e * 4 + 3];
        }

#pragma unroll
        for (int off = 16; off > 0; off >>= 1)
            val += __shfl_down_sync(0xFFFFFFFFu, val, off);
        __shared__ float she[8];
        int lane = threadIdx.x & 31;
        int warp = threadIdx.x >> 5;
        if (lane == 0) she[warp] = val;
        __syncthreads();
        if (threadIdx.x == 0) {
            float s = 0.f;
#pragma unroll
            for (int w = 0; w < 8; ++w) s += she[w];
            atomicAdd(&g_el_accum, (double)s);
        }
    }

    // ---------------- completion ticket + final output write ----------------
    if (threadIdx.x == 0) {
        __threadfence();
        unsigned int t = atomicAdd(&g_done, 1u);
        if (t == (unsigned int)(TOTAL_BLOCKS - 1)) {
            __threadfence();
            double dt = (double)ts_ptr[0];
            double inv_h = 1.0 / dt;
            double coeff = inv_h * inv_h * 0.5;
            double kin = coeff * g_kin_accum;
            double el  = g_el_accum;
            out[0] = (float)(kin + el);
            out[1] = (float)kin;
            out[2] = (float)el;
        }
    }
}

// ---------------------------------------------------------------------------
// Launch — delta, then mega as a PDL secondary so its blocks can prefetch M
// into L2 while delta drains.
// ---------------------------------------------------------------------------
extern "C" void kernel_launch(void* const* d_in, const int* in_sizes, int n_in,
                              void* d_out, int out_size)
{
    const float* next_pos = (const float*)d_in[0];
    const float* pos      = (const float*)d_in[1];
    const float* vel      = (const float*)d_in[2];
    const float* ext      = (const float*)d_in[3];
    const float* M        = (const float*)d_in[4];
    const int*   elems    = (const int*)d_in[5];
    const float* poly     = (const float*)d_in[6];
    const float* measure  = (const float*)d_in[7];
    const float* lam      = (const float*)d_in[8];
    const float* mu       = (const float*)d_in[9];
    const float* ts       = (const float*)d_in[10];
    float* out = (float*)d_out;

    delta_kernel<<<(V + 255) / 256, 256>>>(next_pos, pos, vel, ext, ts);

    cudaLaunchConfig_t cfg = {};
    cfg.gridDim  = dim3(TOTAL_BLOCKS, 1, 1);
    cfg.blockDim = dim3(256, 1, 1);
    cfg.dynamicSmemBytes = 0;
    cfg.stream = 0;   // legacy default stream (same as <<<>>>; capture-safe)
    cudaLaunchAttribute attr[1];
    attr[0].id = cudaLaunchAttributeProgrammaticStreamSerialization;
    attr[0].val.programmaticStreamSerializationAllowed = 1;
    cfg.attrs = attr;
    cfg.numAttrs = 1;
    cudaLaunchKernelEx(&cfg, mega_kernel, M, next_pos, elems, poly, measure,
                       lam, mu, ts, out);
}